// round 1
// baseline (speedup 1.0000x reference)
#include <cuda_runtime.h>

// Problem constants (B=1, H=8, N=2048, D=64, causal mask always on)
#define HH 8
#define NN 2048
#define DD 64
#define BI 64
#define BJ 64
#define NT (NN / BI)          // 32 i-tiles
#define LDS 68                // padded smem row stride (floats)
#define THREADS 256

// Dynamic smem layout (floats):
//  Qs : [64][68]   = 4352
//  Ks : [64][68]   = 4352   (reused for V tile)
//  Rs : [127][68]  -> reserve 8704
//  Ws : [64][68]   = 4352
// total 21760 floats = 87040 bytes
#define OFF_Q 0
#define OFF_K 4352
#define OFF_R 8704
#define OFF_W 17408
#define SMEM_FLOATS 21760

__device__ __forceinline__ void load_tile64(float* dst, const float* __restrict__ src, int tid) {
    // 64 rows x 64 cols, src row-major (stride 64), dst stride LDS
    const float4* s4 = reinterpret_cast<const float4*>(src);
#pragma unroll
    for (int p = tid; p < 64 * 16; p += THREADS) {
        int r = p >> 4, c = p & 15;
        *reinterpret_cast<float4*>(&dst[r * LDS + c * 4]) = s4[p];
    }
}

__device__ __forceinline__ void load_rband(float* dst, const float* __restrict__ rpe, int rbase, int tid) {
    // 127 rows x 64 cols of rpe starting at row rbase
    const float4* s4 = reinterpret_cast<const float4*>(rpe);
    for (int p = tid; p < 127 * 16; p += THREADS) {
        int r = p >> 4, c = p & 15;
        *reinterpret_cast<float4*>(&dst[r * LDS + c * 4]) = s4[(rbase + r) * 16 + c];
    }
}

__global__ __launch_bounds__(THREADS)
void fastmax_kernel(const float* __restrict__ q,
                    const float* __restrict__ k,
                    const float* __restrict__ v,
                    const float* __restrict__ rpe,
                    float* __restrict__ out) {
    extern __shared__ float sm[];
    float* Qs = sm + OFF_Q;
    float* Ks = sm + OFF_K;   // also V tile
    float* Rs = sm + OFF_R;
    float* Ws = sm + OFF_W;

    const int tid = threadIdx.x;
    const int tx = tid & 15;       // 0..15
    const int ty = tid >> 4;       // 0..15
    const int h = blockIdx.y;
    const int pair = blockIdx.x;   // 0..15

    const float* qh = q + (size_t)h * NN * DD;
    const float* kh = k + (size_t)h * NN * DD;
    const float* vh = v + (size_t)h * NN * DD;
    float* oh = out + (size_t)h * NN * DD;

    // Two i-tiles per block: it and NT-1-it  ->  (it+1)+(NT-it) = 33 j-steps, balanced.
#pragma unroll 1
    for (int phase = 0; phase < 2; ++phase) {
        const int it = phase ? (NT - 1 - pair) : pair;
        const int i0 = it * BI;

        __syncthreads();                    // previous phase fully done with smem
        load_tile64(Qs, qh + (size_t)i0 * DD, tid);

        // Persistent accumulators: rows ii = ty + 16a
        float o_acc[4][4];
        float dpart[4];
#pragma unroll
        for (int a = 0; a < 4; ++a) {
            dpart[a] = 0.f;
#pragma unroll
            for (int c = 0; c < 4; ++c) o_acc[a][c] = 0.f;
        }

#pragma unroll 1
        for (int jt = 0; jt <= it; ++jt) {
            const int j0 = jt * BJ;
            const int rbase = i0 - j0 + (NN - 1) - 63;   // always in [0, 2N-2-126]

            __syncthreads();   // Q loaded (first iter) / prev stage-B done with Ks, Ws
            load_tile64(Ks, kh + (size_t)j0 * DD, tid);
            load_rband(Rs, rpe, rbase, tid);
            __syncthreads();

            // ---- Stage A: S tile (rows ii=ty+16a, cols jj=tx+16b) ----
            float s[4][4];
#pragma unroll
            for (int a = 0; a < 4; ++a)
#pragma unroll
                for (int b = 0; b < 4; ++b) s[a][b] = 0.f;

            const float* Qr = Qs + ty * LDS;                 // + 16a*LDS per a
            const float* Kr = Ks + tx * LDS;                 // + 16b*LDS per b
            const float* Rr = Rs + (ty - tx + 15) * LDS;     // + 16u*LDS per u

#pragma unroll 2
            for (int d4 = 0; d4 < 16; ++d4) {
                float4 kb[4], ru[7];
#pragma unroll
                for (int b = 0; b < 4; ++b)
                    kb[b] = *reinterpret_cast<const float4*>(Kr + b * 16 * LDS + d4 * 4);
#pragma unroll
                for (int u = 0; u < 7; ++u)
                    ru[u] = *reinterpret_cast<const float4*>(Rr + u * 16 * LDS + d4 * 4);
#pragma unroll
                for (int a = 0; a < 4; ++a) {
                    float4 qa = *reinterpret_cast<const float4*>(Qr + a * 16 * LDS + d4 * 4);
#pragma unroll
                    for (int b = 0; b < 4; ++b) {
                        float4 kk4 = kb[b];
                        float4 rr4 = ru[a - b + 3];   // t = (ii-jj)+63
                        float acc = s[a][b];
                        acc += qa.x * (kk4.x + rr4.x);
                        acc += qa.y * (kk4.y + rr4.y);
                        acc += qa.z * (kk4.z + rr4.z);
                        acc += qa.w * (kk4.w + rr4.w);
                        s[a][b] = acc;
                    }
                }
            }

            // Taylor-2 weight + causal mask (only diagonal tile can mask)
            const bool diag = (jt == it);
#pragma unroll
            for (int a = 0; a < 4; ++a) {
                const int ii = ty + 16 * a;
#pragma unroll
                for (int b = 0; b < 4; ++b) {
                    const int jj = tx + 16 * b;
                    float sv = s[a][b];
                    float w = 1.0f + sv + 0.5f * sv * sv;
                    if (diag && (jj > ii)) w = 0.0f;
                    dpart[a] += w;
                    Ws[ii * LDS + jj] = w;
                }
            }

            __syncthreads();                 // stage A done reading Ks
            load_tile64(Ks, vh + (size_t)j0 * DD, tid);   // V tile over K buffer
            __syncthreads();

            // ---- Stage B: O += W @ V  (rows ii=ty+16a, cols dd=tx*4..tx*4+3) ----
#pragma unroll 4
            for (int jj = 0; jj < BJ; ++jj) {
                float4 vv = *reinterpret_cast<const float4*>(&Ks[jj * LDS + tx * 4]);
#pragma unroll
                for (int a = 0; a < 4; ++a) {
                    float w = Ws[(ty + 16 * a) * LDS + jj];
                    o_acc[a][0] += w * vv.x;
                    o_acc[a][1] += w * vv.y;
                    o_acc[a][2] += w * vv.z;
                    o_acc[a][3] += w * vv.w;
                }
            }
        }

        // ---- Denominator reduction across tx, then write output ----
        __syncthreads();                     // stage B done reading Ws
#pragma unroll
        for (int a = 0; a < 4; ++a)
            Ws[(ty + 16 * a) * 16 + tx] = dpart[a];
        __syncthreads();

#pragma unroll
        for (int a = 0; a < 4; ++a) {
            const int ii = ty + 16 * a;
            float den = 0.f;
#pragma unroll
            for (int x = 0; x < 16; ++x) den += Ws[ii * 16 + x];
            const float inv = 1.0f / den;
            float4 r;
            r.x = o_acc[a][0] * inv;
            r.y = o_acc[a][1] * inv;
            r.z = o_acc[a][2] * inv;
            r.w = o_acc[a][3] * inv;
            *reinterpret_cast<float4*>(&oh[(size_t)(i0 + ii) * DD + tx * 4]) = r;
        }
    }
}

extern "C" void kernel_launch(void* const* d_in, const int* in_sizes, int n_in,
                              void* d_out, int out_size) {
    const float* q   = (const float*)d_in[0];
    const float* k   = (const float*)d_in[1];
    const float* v   = (const float*)d_in[2];
    const float* rpe = (const float*)d_in[3];
    // d_in[4] = mask (always 1 / causal for this problem)
    float* out = (float*)d_out;

    const size_t smem = SMEM_FLOATS * sizeof(float);   // 87040 B
    cudaFuncSetAttribute(fastmax_kernel, cudaFuncAttributeMaxDynamicSharedMemorySize, (int)smem);

    dim3 grid(NT / 2, HH);   // 16 balanced i-tile pairs x 8 heads = 128 blocks
    fastmax_kernel<<<grid, THREADS, smem>>>(q, k, v, rpe, out);
}

// round 11
// speedup vs baseline: 2.6253x; 2.6253x over previous
#include <cuda_runtime.h>
#include <cuda_bf16.h>
#include <cstdint>

// B=1, H=8, N=2048, D=64, causal.
#define HH 8
#define NN 2048
#define DD 64
#define BT 64              // i/j tile
#define NT 32              // i-tiles (NN/BT)
#define THREADS 256
#define LDB 144            // bytes per bf16 tile row (72 halves: 64 + 8 pad)

// SMEM byte offsets
#define QHI 0
#define QLO 9216
#define KHI 18432
#define KLO 27648
#define RHI 36864
#define RLO 46080
#define VTHI 55296
#define VTLO 64512
#define RING 73728                 // 64 rows x 260 floats
#define RING_STRIDE 260
#define SDEN (RING + 64 * RING_STRIDE * 4)   // 140288
#define ORED RING                  // reuse ring for O reduction
#define ORED_STRIDE 68
#define SMEM_TOTAL (SDEN + 64 * 2 * 4)       // 140800

__device__ __forceinline__ uint32_t smem_u32(const void* p) {
    uint32_t a;
    asm("{ .reg .u64 t; cvta.to.shared.u64 t, %1; cvt.u32.u64 %0, t; }" : "=r"(a) : "l"(p));
    return a;
}
__device__ __forceinline__ void ldm4(unsigned* r, uint32_t addr) {
    asm volatile("ldmatrix.sync.aligned.m8n8.x4.shared.b16 {%0,%1,%2,%3}, [%4];"
                 : "=r"(r[0]), "=r"(r[1]), "=r"(r[2]), "=r"(r[3]) : "r"(addr));
}
__device__ __forceinline__ void mma_bf16(float* c, const unsigned* a, const unsigned* b) {
    asm volatile("mma.sync.aligned.m16n8k16.row.col.f32.bf16.bf16.f32 "
                 "{%0,%1,%2,%3},{%4,%5,%6,%7},{%8,%9},{%0,%1,%2,%3};"
                 : "+f"(c[0]), "+f"(c[1]), "+f"(c[2]), "+f"(c[3])
                 : "r"(a[0]), "r"(a[1]), "r"(a[2]), "r"(a[3]), "r"(b[0]), "r"(b[1]));
}
__device__ __forceinline__ unsigned pk(float a, float b) {
    __nv_bfloat162 t = __floats2bfloat162_rn(a, b);
    return (unsigned)__bfloat16_as_ushort(t.x) | ((unsigned)__bfloat16_as_ushort(t.y) << 16);
}
// residual of float after bf16 truncation
__device__ __forceinline__ float resid(float x, __nv_bfloat16 h) { return x - __bfloat162float(h); }

__device__ __forceinline__ void cvt_store(char* smc, int hioff, int looff, int r, int c4, float4 v) {
    __nv_bfloat16 hx = __float2bfloat16(v.x), hy = __float2bfloat16(v.y);
    __nv_bfloat16 hz = __float2bfloat16(v.z), hw = __float2bfloat16(v.w);
    uint2 hi, lo;
    hi.x = (unsigned)__bfloat16_as_ushort(hx) | ((unsigned)__bfloat16_as_ushort(hy) << 16);
    hi.y = (unsigned)__bfloat16_as_ushort(hz) | ((unsigned)__bfloat16_as_ushort(hw) << 16);
    lo.x = pk(resid(v.x, hx), resid(v.y, hy));
    lo.y = pk(resid(v.z, hz), resid(v.w, hw));
    *(uint2*)(smc + hioff + r * LDB + c4 * 8) = hi;
    *(uint2*)(smc + looff + r * LDB + c4 * 8) = lo;
}

// B-fragment ldmatrix address: n-rows n0..n0+15, k16 chunk at kbyte (bytes)
__device__ __forceinline__ uint32_t baddr(uint32_t base, int n0, int kbyte, int lane) {
    int row = n0 + (lane & 7) + ((lane >> 4) << 3);
    int chunk = (lane >> 3) & 1;
    return base + row * LDB + chunk * 16 + kbyte;
}

__global__ __launch_bounds__(THREADS, 1)
void fastmax_mma(const float* __restrict__ q,
                 const float* __restrict__ k,
                 const float* __restrict__ v,
                 const float* __restrict__ rpe,
                 float* __restrict__ out) {
    extern __shared__ char smc[];
    const uint32_t sb = smem_u32(smc);
    float* ringf = (float*)(smc + RING);
    float* sden = (float*)(smc + SDEN);

    const int tid = threadIdx.x;
    const int lane = tid & 31, w = tid >> 5;
    const int g = w >> 1, h = w & 1;       // row-group 0..3, n-half 0..1
    const int pairb = blockIdx.x;          // 0..15
    const int head = blockIdx.y;

    const float4* qh4 = (const float4*)(q + (size_t)head * NN * DD);
    const float4* kh4 = (const float4*)(k + (size_t)head * NN * DD);
    const float*  vh  = v + (size_t)head * NN * DD;
    const float4* rp4 = (const float4*)rpe;
    float* oh = out + (size_t)head * NN * DD;

    const int lq = lane >> 2;              // 0..7 (row within 8)
    const int lr = lane & 3;               // col-pair selector

#pragma unroll 1
    for (int phase = 0; phase < 2; ++phase) {
        const int it = phase ? (NT - 1 - pairb) : pairb;
        const int i0 = it * BT;
        const int njt = it + 1;

        __syncthreads();
        // ---- Q tile -> smem hi/lo ----
#pragma unroll
        for (int p = tid; p < 64 * 16; p += THREADS) {
            int r = p >> 4, c4 = p & 15;
            cvt_store(smc, QHI, QLO, r, c4, qh4[(size_t)(i0 + r) * 16 + c4]);
        }
        __syncthreads();

        // ---- Q A-fragments (persist whole phase) ----
        unsigned qa_h[4][4], qa_l[4][4];
        {
            int row = 16 * g + (lane & 15);
            int ch = lane >> 4;
#pragma unroll
            for (int kk = 0; kk < 4; ++kk) {
                ldm4(qa_h[kk], sb + QHI + row * LDB + ch * 16 + kk * 32);
                ldm4(qa_l[kk], sb + QLO + row * LDB + ch * 16 + kk * 32);
            }
        }

        float oacc[8][4];
#pragma unroll
        for (int t = 0; t < 8; ++t)
#pragma unroll
            for (int e = 0; e < 4; ++e) oacc[t][e] = 0.f;
        float dp0 = 0.f, dp1 = 0.f;

#pragma unroll 1
        for (int jt = 0; jt < njt; ++jt) {
            const int j0 = jt * BT;
            __syncthreads();   // prev step's smem consumers done

            // ---- K tile ----
#pragma unroll
            for (int p = tid; p < 64 * 16; p += THREADS) {
                int r = p >> 4, c4 = p & 15;
                cvt_store(smc, KHI, KLO, r, c4, kh4[(size_t)(j0 + r) * 16 + c4]);
            }
            // ---- V tile transposed: Vt[d][j], rows d, cols j ----
#pragma unroll
            for (int p = tid; p < 1024; p += THREADS) {
                int d = p & 63, jg = p >> 6;     // jg = group of 4 j's
                float4 vv;
                vv.x = vh[(size_t)(j0 + 4 * jg + 0) * DD + d];
                vv.y = vh[(size_t)(j0 + 4 * jg + 1) * DD + d];
                vv.z = vh[(size_t)(j0 + 4 * jg + 2) * DD + d];
                vv.w = vh[(size_t)(j0 + 4 * jg + 3) * DD + d];
                cvt_store(smc, VTHI, VTLO, d, jg, vv);
            }

            // ---- R chunk(s): load -> P gemm -> ring ----
            const int t0 = i0 - j0 + 1984;       // lowest rpe row needed this step
            const int nch = (jt == 0) ? 2 : 1;
#pragma unroll 1
            for (int c = 0; c < nch; ++c) {
                const int tb = t0 + 64 * (nch - 1 - c);
#pragma unroll
                for (int p = tid; p < 64 * 16; p += THREADS) {
                    int r = p >> 4, c4 = p & 15;
                    int m = tb + r; if (m > 2 * NN - 2) m = 2 * NN - 2;  // clamped rows never gathered
                    cvt_store(smc, RHI, RLO, r, c4, rp4[(size_t)m * 16 + c4]);
                }
                __syncthreads();

                float pacc[4][4];
#pragma unroll
                for (int m = 0; m < 4; ++m)
#pragma unroll
                    for (int e = 0; e < 4; ++e) pacc[m][e] = 0.f;
#pragma unroll
                for (int kk = 0; kk < 4; ++kk) {
                    unsigned bh[8], bl[8];
                    ldm4(bh,     baddr(sb + RHI, 32 * h,      kk * 32, lane));
                    ldm4(bh + 4, baddr(sb + RHI, 32 * h + 16, kk * 32, lane));
#pragma unroll
                    for (int m = 0; m < 4; ++m) mma_bf16(pacc[m], qa_h[kk], bh + 2 * m);
#pragma unroll
                    for (int m = 0; m < 4; ++m) mma_bf16(pacc[m], qa_l[kk], bh + 2 * m);
                    ldm4(bl,     baddr(sb + RLO, 32 * h,      kk * 32, lane));
                    ldm4(bl + 4, baddr(sb + RLO, 32 * h + 16, kk * 32, lane));
#pragma unroll
                    for (int m = 0; m < 4; ++m) mma_bf16(pacc[m], qa_h[kk], bl + 2 * m);
                }
                // ring store (chunk's 64 slots are contiguous: tb multiple of 64)
                const int s0 = tb & 255;
                const int rr = 16 * g + lq;
                const int cc = 32 * h + 2 * lr;
#pragma unroll
                for (int m = 0; m < 4; ++m) {
                    int col = cc + 8 * m;
                    *(float2*)(ringf + rr * RING_STRIDE + s0 + col) =
                        make_float2(pacc[m][0], pacc[m][1]);
                    *(float2*)(ringf + (rr + 8) * RING_STRIDE + s0 + col) =
                        make_float2(pacc[m][2], pacc[m][3]);
                }
                __syncthreads();
            }

            // ---- S = Q Kt ----
            float sacc[4][4];
#pragma unroll
            for (int m = 0; m < 4; ++m)
#pragma unroll
                for (int e = 0; e < 4; ++e) sacc[m][e] = 0.f;
#pragma unroll
            for (int kk = 0; kk < 4; ++kk) {
                unsigned bh[8], bl[8];
                ldm4(bh,     baddr(sb + KHI, 32 * h,      kk * 32, lane));
                ldm4(bh + 4, baddr(sb + KHI, 32 * h + 16, kk * 32, lane));
#pragma unroll
                for (int m = 0; m < 4; ++m) mma_bf16(sacc[m], qa_h[kk], bh + 2 * m);
#pragma unroll
                for (int m = 0; m < 4; ++m) mma_bf16(sacc[m], qa_l[kk], bh + 2 * m);
                ldm4(bl,     baddr(sb + KLO, 32 * h,      kk * 32, lane));
                ldm4(bl + 4, baddr(sb + KLO, 32 * h + 16, kk * 32, lane));
#pragma unroll
                for (int m = 0; m < 4; ++m) mma_bf16(sacc[m], qa_h[kk], bl + 2 * m);
            }

            // ---- epilogue: s += ring gather, w = 1+s+s^2/2, mask, den, W frags ----
            const int rr = 16 * g + lq;
            const int gi0 = i0 + rr, gi1 = gi0 + 8;
            unsigned wh[2][4], wl[2][4];
#pragma unroll
            for (int m = 0; m < 4; ++m) {
                int lc = 32 * h + 8 * m + 2 * lr;
                int gj = j0 + lc;
                int t00 = gi0 - gj + 2047;
                float s00 = sacc[m][0] + ringf[rr * RING_STRIDE + (t00 & 255)];
                float s01 = sacc[m][1] + ringf[rr * RING_STRIDE + ((t00 - 1) & 255)];
                float s10 = sacc[m][2] + ringf[(rr + 8) * RING_STRIDE + ((t00 + 8) & 255)];
                float s11 = sacc[m][3] + ringf[(rr + 8) * RING_STRIDE + ((t00 + 7) & 255)];
                float w00 = 1.0f + s00 + 0.5f * s00 * s00;
                float w01 = 1.0f + s01 + 0.5f * s01 * s01;
                float w10 = 1.0f + s10 + 0.5f * s10 * s10;
                float w11 = 1.0f + s11 + 0.5f * s11 * s11;
                if (gj > gi0) w00 = 0.f;
                if (gj + 1 > gi0) w01 = 0.f;
                if (gj > gi1) w10 = 0.f;
                if (gj + 1 > gi1) w11 = 0.f;
                dp0 += w00 + w01;
                dp1 += w10 + w11;
                __nv_bfloat16 h00 = __float2bfloat16(w00), h01 = __float2bfloat16(w01);
                __nv_bfloat16 h10 = __float2bfloat16(w10), h11 = __float2bfloat16(w11);
                int kk = m >> 1, odd = m & 1;
                wh[kk][odd * 2 + 0] = (unsigned)__bfloat16_as_ushort(h00) |
                                      ((unsigned)__bfloat16_as_ushort(h01) << 16);
                wh[kk][odd * 2 + 1] = (unsigned)__bfloat16_as_ushort(h10) |
                                      ((unsigned)__bfloat16_as_ushort(h11) << 16);
                wl[kk][odd * 2 + 0] = pk(resid(w00, h00), resid(w01, h01));
                wl[kk][odd * 2 + 1] = pk(resid(w10, h10), resid(w11, h11));
            }

            // ---- O += W @ V (k = this warp's 32 j-cols; n = d 0..63) ----
#pragma unroll
            for (int kk = 0; kk < 2; ++kk) {
                int kbyte = (32 * h + 16 * kk) * 2;
#pragma unroll
                for (int nb2 = 0; nb2 < 4; ++nb2) {
                    unsigned vbh[4], vbl[4];
                    ldm4(vbh, baddr(sb + VTHI, 16 * nb2, kbyte, lane));
                    mma_bf16(oacc[2 * nb2],     wh[kk], vbh);
                    mma_bf16(oacc[2 * nb2 + 1], wh[kk], vbh + 2);
                    mma_bf16(oacc[2 * nb2],     wl[kk], vbh);
                    mma_bf16(oacc[2 * nb2 + 1], wl[kk], vbh + 2);
                    ldm4(vbl, baddr(sb + VTLO, 16 * nb2, kbyte, lane));
                    mma_bf16(oacc[2 * nb2],     wh[kk], vbl);
                    mma_bf16(oacc[2 * nb2 + 1], wh[kk], vbl + 2);
                }
            }
        } // jt

        // ---- reductions + output ----
        float d0 = dp0, d1 = dp1;
        d0 += __shfl_xor_sync(0xffffffffu, d0, 1);
        d0 += __shfl_xor_sync(0xffffffffu, d0, 2);
        d1 += __shfl_xor_sync(0xffffffffu, d1, 1);
        d1 += __shfl_xor_sync(0xffffffffu, d1, 2);
        __syncthreads();   // ring gathers done -> safe to reuse ring as ORED
        if (lr == 0) {
            sden[(16 * g + lq) * 2 + h] = d0;
            sden[(16 * g + lq + 8) * 2 + h] = d1;
        }
        if (h == 1) {
#pragma unroll
            for (int nb = 0; nb < 8; ++nb) {
                int col = 8 * nb + 2 * lr;
                *(float2*)(smc + ORED + ((g * 16 + lq) * ORED_STRIDE + col) * 4) =
                    make_float2(oacc[nb][0], oacc[nb][1]);
                *(float2*)(smc + ORED + ((g * 16 + lq + 8) * ORED_STRIDE + col) * 4) =
                    make_float2(oacc[nb][2], oacc[nb][3]);
            }
        }
        __syncthreads();
        if (h == 0) {
            float den0 = sden[(16 * g + lq) * 2] + sden[(16 * g + lq) * 2 + 1];
            float den1 = sden[(16 * g + lq + 8) * 2] + sden[(16 * g + lq + 8) * 2 + 1];
            float inv0 = 1.0f / den0, inv1 = 1.0f / den1;
#pragma unroll
            for (int nb = 0; nb < 8; ++nb) {
                int col = 8 * nb + 2 * lr;
                float2 p0 = *(float2*)(smc + ORED + ((g * 16 + lq) * ORED_STRIDE + col) * 4);
                float2 p1 = *(float2*)(smc + ORED + ((g * 16 + lq + 8) * ORED_STRIDE + col) * 4);
                float2 r0 = make_float2((oacc[nb][0] + p0.x) * inv0, (oacc[nb][1] + p0.y) * inv0);
                float2 r1 = make_float2((oacc[nb][2] + p1.x) * inv1, (oacc[nb][3] + p1.y) * inv1);
                *(float2*)(oh + (size_t)(i0 + 16 * g + lq) * DD + col) = r0;
                *(float2*)(oh + (size_t)(i0 + 16 * g + lq + 8) * DD + col) = r1;
            }
        }
    } // phase
}

extern "C" void kernel_launch(void* const* d_in, const int* in_sizes, int n_in,
                              void* d_out, int out_size) {
    const float* q   = (const float*)d_in[0];
    const float* k   = (const float*)d_in[1];
    const float* v   = (const float*)d_in[2];
    const float* rpe = (const float*)d_in[3];
    float* out = (float*)d_out;

    cudaFuncSetAttribute(fastmax_mma,
                         cudaFuncAttributeMaxDynamicSharedMemorySize, SMEM_TOTAL);
    dim3 grid(NT / 2, HH);    // 16 pairs x 8 heads = 128 blocks
    fastmax_mma<<<grid, THREADS, SMEM_TOTAL>>>(q, k, v, rpe, out);
}